// round 16
// baseline (speedup 1.0000x reference)
#include <cuda_runtime.h>
#include <cuda_fp16.h>
#include <stdint.h>

#define BN_EPS 1e-3f

// Segment layout: atom rows d0 [0,4096) d1 [4096,16384) d2 [16384,36864) d3 [36864,57344) d4 [57344,65536)
// rel rows: d1 [0,12288) d2 [12288,32768) d3 [32768,53248) d4 [53248,61440)

// -------- scratch (static device globals) --------
__device__ __half   g_atomh[65536 * 80];
__device__ __half   g_bufAh[65536 * 256];
__device__ __half   g_bufBh[65536 * 256];
__device__ __half   g_w1h  [9 * 80 * 256];
__device__ __half   g_w2h  [9 * 256 * 256];
__device__ __half   g_wdh  [256 * 512];
__device__ float    g_sum  [1024 * 512];
__device__ unsigned g_maxu [1024 * 512];

// ======================= asm helpers =======================
__device__ __forceinline__ uint32_t smem_u32(const void* p) {
    uint32_t a;
    asm("{ .reg .u64 t; cvta.to.shared.u64 t, %1; cvt.u32.u64 %0, t; }" : "=r"(a) : "l"(p));
    return a;
}
__device__ __forceinline__ uint32_t pkf16(float lo, float hi) {
    uint32_t r; asm("cvt.rn.f16x2.f32 %0, %1, %2;" : "=r"(r) : "f"(hi), "f"(lo));
    return r;
}
__device__ __forceinline__ void cp16(uint32_t dst, const void* src) {
    asm volatile("cp.async.cg.shared.global [%0], [%1], 16;" :: "r"(dst), "l"(src));
}
#define CP_COMMIT() asm volatile("cp.async.commit_group;" ::: "memory")
template<int N>
__device__ __forceinline__ void cp_wait() {
    asm volatile("cp.async.wait_group %0;" :: "n"(N) : "memory");
}
__device__ __forceinline__ void sts128(uint32_t a, uint4 v) {
    asm volatile("st.shared.v4.b32 [%0], {%1,%2,%3,%4};"
        :: "r"(a), "r"(v.x), "r"(v.y), "r"(v.z), "r"(v.w));
}

__device__ __forceinline__ void ldsm_x4(uint32_t& r0, uint32_t& r1, uint32_t& r2, uint32_t& r3,
                                        uint32_t addr) {
    asm volatile("ldmatrix.sync.aligned.m8n8.x4.shared.b16 {%0,%1,%2,%3}, [%4];"
        : "=r"(r0), "=r"(r1), "=r"(r2), "=r"(r3) : "r"(addr));
}
__device__ __forceinline__ void ldsm_x2t(uint32_t& r0, uint32_t& r1, uint32_t addr) {
    asm volatile("ldmatrix.sync.aligned.m8n8.x2.trans.shared.b16 {%0,%1}, [%2];"
        : "=r"(r0), "=r"(r1) : "r"(addr));
}
__device__ __forceinline__ void mma16(float* d, const uint32_t* a, const uint32_t* b) {
    asm volatile("mma.sync.aligned.m16n8k16.row.col.f32.f16.f16.f32 "
        "{%0,%1,%2,%3}, {%4,%5,%6,%7}, {%8,%9}, {%0,%1,%2,%3};"
        : "+f"(d[0]), "+f"(d[1]), "+f"(d[2]), "+f"(d[3])
        : "r"(a[0]), "r"(a[1]), "r"(a[2]), "r"(a[3]), "r"(b[0]), "r"(b[1]));
}

__device__ __forceinline__ unsigned ford(float f) {
    unsigned u = __float_as_uint(f);
    return u ^ (unsigned)(((int)u >> 31) | 0x80000000);
}
__device__ __forceinline__ float funord(unsigned v) {
    unsigned u = (v & 0x80000000u) ? (v ^ 0x80000000u) : ~v;
    return __uint_as_float(u);
}

__device__ __forceinline__ void acc8(float2 s[4], uint4 v) {
    s[0].x += __low2float(*(__half2*)&v.x);  s[0].y += __high2float(*(__half2*)&v.x);
    s[1].x += __low2float(*(__half2*)&v.y);  s[1].y += __high2float(*(__half2*)&v.y);
    s[2].x += __low2float(*(__half2*)&v.z);  s[2].y += __high2float(*(__half2*)&v.z);
    s[3].x += __low2float(*(__half2*)&v.w);  s[3].y += __high2float(*(__half2*)&v.w);
}

// ======================= GEMM pieces: 256 threads, 128x128 tile =======================
template<int BKC> struct GP {
    static constexpr int ARH  = BKC + 8;
    static constexpr int ASTG = 128 * ARH * 2;
    static constexpr int BSTG = BKC * 136 * 2;
    static constexpr int STG  = ASTG + BSTG;
    static constexpr int NST  = (BKC == 80) ? 2 : 3;
    static constexpr int SMEM = NST * STG;
};

// async copy of A tile (direct rows) into stage
template<int BKC>
__device__ __forceinline__ void issue_A(
    uint32_t sa, const __half* __restrict__ A, int lda, int kt, int tid)
{
    constexpr int AU  = BKC / 8;
    constexpr int APT = 128 * AU / 256;
#pragma unroll
    for (int h = 0; h < APT; h++) {
        int id = tid + h * 256;
        int row = id / AU, u = id % AU;
        cp16(sa + (row * GP<BKC>::ARH + u * 8) * 2, A + (long)row * lda + kt + u * 8);
    }
}

// fused gather-sum A tile: rows = sum of up to 4 neighbor rows of X (LDG + STS)
template<int BKC>
__device__ __forceinline__ void issue_A_gather(
    uint32_t sa, const __half* __restrict__ X, int lda,
    const int* __restrict__ adj, int dd, int li0, int kt, int tid)
{
    constexpr int AU  = BKC / 8;
    constexpr int APT = 128 * AU / 256;
#pragma unroll
    for (int h = 0; h < APT; h++) {
        int id = tid + h * 256;
        int row = id / AU, u = id % AU;
        int li = li0 + row;
        float2 s[4];
        s[0] = s[1] = s[2] = s[3] = make_float2(0.f, 0.f);
        for (int j = 0; j < dd; j++) {
            long n = adj[li * dd + j];
            uint4 v = *reinterpret_cast<const uint4*>(X + n * lda + kt + u * 8);
            acc8(s, v);
        }
        uint4 o;
        o.x = pkf16(s[0].x, s[0].y); o.y = pkf16(s[1].x, s[1].y);
        o.z = pkf16(s[2].x, s[2].y); o.w = pkf16(s[3].x, s[3].y);
        sts128(sa + (row * GP<BKC>::ARH + u * 8) * 2, o);
    }
}

template<int BKC>
__device__ __forceinline__ void issue_B(
    uint32_t sb, const __half* __restrict__ B, int ldb, int col0, int kt, int tid)
{
    constexpr int BPT = BKC * 16 / 256;
#pragma unroll
    for (int h = 0; h < BPT; h++) {
        int id = tid + h * 256;
        int row = id >> 4, u = id & 15;
        cp16(sb + (row * 136 + u * 8) * 2, B + (long)(kt + row) * ldb + col0 + u * 8);
    }
}

template<int BKC>
__device__ __forceinline__ void compute_stage(
    uint32_t sa, uint32_t sb, float acc[16][4], int wm, int wn, int lane)
{
    const int arow = lane & 15, asel = (lane >> 4) * 8;
#pragma unroll
    for (int ks = 0; ks < BKC / 16; ks++) {
        uint32_t a[4][4];
#pragma unroll
        for (int mt = 0; mt < 4; mt++) {
            int m0 = wm * 64 + mt * 16;
            ldsm_x4(a[mt][0], a[mt][1], a[mt][2], a[mt][3],
                    sa + ((m0 + arow) * GP<BKC>::ARH + ks * 16 + asel) * 2);
        }
        uint32_t b[4][2];
        int krow = ks * 16 + (lane & 15);
#pragma unroll
        for (int nt = 0; nt < 4; nt++) {
            int n0 = wn * 32 + nt * 8;
            ldsm_x2t(b[nt][0], b[nt][1], sb + (krow * 136 + n0) * 2);
        }
#pragma unroll
        for (int mt = 0; mt < 4; mt++)
#pragma unroll
            for (int nt = 0; nt < 4; nt++)
                mma16(acc[mt * 4 + nt], a[mt], b[nt]);
    }
}

// ======================= conv GEMM (fp16, fused neighbor-gather, 2 CTAs/SM) ====
template<int BKC>
__global__ void __launch_bounds__(256, 2)
conv_gemm_t(const __half* __restrict__ X, int lda, int KCH,
            const __half* __restrict__ Wh,
            const float* __restrict__ bz,
            const float* __restrict__ bnp,
            const int* __restrict__ a1, const int* __restrict__ a2,
            const int* __restrict__ a3, const int* __restrict__ a4,
            __half* __restrict__ Y)
{
    constexpr int NST = GP<BKC>::NST;
    extern __shared__ char dyn[];
    const uint32_t sa0 = smem_u32(dyn);
    __shared__ float s_sc[128], s_sh[128], s_bi[128];

    const int tid = threadIdx.x;
    const int lane = tid & 31, wid = tid >> 5;
    const int gid = lane >> 2, tig = lane & 3;
    const int wm = wid & 1, wn = wid >> 1;
    const int row0 = blockIdx.y * 128;
    const int col0 = blockIdx.x * 128;
    const int d = (row0 < 4096) ? 0 : (row0 < 16384) ? 1 : (row0 < 36864) ? 2
                : (row0 < 57344) ? 3 : 4;
    const int* adj = (d == 1) ? a1 : (d == 2) ? a2 : (d == 3) ? a3 : a4;
    const int li0 = (d > 0) ? (row0 - 4096
                    - ((d == 1) ? 0 : (d == 2) ? 12288 : (d == 3) ? 32768 : 53248)) : 0;

    if (tid < 128) {
        int c = col0 + tid;
        float bias = (d == 0) ? bz[8 * 256 + c]
                              : bz[(2 * d - 2) * 256 + c] + bz[(2 * d - 1) * 256 + c];
        float gg = bnp[c], be = bnp[256 + c], mu = bnp[512 + c], va = bnp[768 + c];
        float sc = gg * rsqrtf(va + BN_EPS);
        s_sc[tid] = sc; s_sh[tid] = be - mu * sc; s_bi[tid] = bias;
    }

    const long wsz = (long)lda * 256;
    const __half* A0 = X + (long)row0 * lda;
    const __half* W0 = Wh + ((d == 0) ? 8 : (2 * d - 1)) * wsz;
    const __half* W1 = (d > 0) ? Wh + (2 * d - 2) * wsz : W0;
    const int T = ((d > 0) ? 2 : 1) * KCH;

    float acc[16][4];
#pragma unroll
    for (int i = 0; i < 16; i++)
        acc[i][0] = acc[i][1] = acc[i][2] = acc[i][3] = 0.f;

    if constexpr (BKC == 80) {
        // conv1: T in {1,2}, NST=2; all chunks upfront. Chunk1 = fused gather pass.
        issue_A<BKC>(sa0, A0, lda, 0, tid);
        issue_B<BKC>(sa0 + GP<BKC>::ASTG, W0, 256, col0, 0, tid);
        CP_COMMIT();
        if (T == 2) {
            uint32_t s1 = sa0 + GP<BKC>::STG;
            issue_B<BKC>(s1 + GP<BKC>::ASTG, W1, 256, col0, 0, tid);
            CP_COMMIT();
            issue_A_gather<BKC>(s1, X, lda, adj, d, li0, 0, tid);
            cp_wait<1>();
            __syncthreads();
            compute_stage<BKC>(sa0, sa0 + GP<BKC>::ASTG, acc, wm, wn, lane);
            cp_wait<0>();
            __syncthreads();
            compute_stage<BKC>(s1, s1 + GP<BKC>::ASTG, acc, wm, wn, lane);
        } else {
            cp_wait<0>();
            __syncthreads();
            compute_stage<BKC>(sa0, sa0 + GP<BKC>::ASTG, acc, wm, wn, lane);
        }
    } else {
#pragma unroll
        for (int c = 0; c < NST - 1; c++) {
            if (c < T) {
                int pass = (c >= KCH), kc = c - pass * KCH;
                uint32_t sbase = sa0 + (c % NST) * GP<BKC>::STG;
                issue_B<BKC>(sbase + GP<BKC>::ASTG, pass ? W1 : W0, 256, col0,
                             kc * BKC, tid);
                if (pass) issue_A_gather<BKC>(sbase, X, lda, adj, d, li0, kc * BKC, tid);
                else      issue_A<BKC>(sbase, A0, lda, kc * BKC, tid);
            }
            CP_COMMIT();
        }
        for (int c = 0; c < T; c++) {
            cp_wait<NST - 2>();
            __syncthreads();
            int n = c + NST - 1;
            if (n < T) {
                int pass = (n >= KCH), kc = n - pass * KCH;
                uint32_t sbase = sa0 + (n % NST) * GP<BKC>::STG;
                issue_B<BKC>(sbase + GP<BKC>::ASTG, pass ? W1 : W0, 256, col0,
                             kc * BKC, tid);
                if (pass) issue_A_gather<BKC>(sbase, X, lda, adj, d, li0, kc * BKC, tid);
                else      issue_A<BKC>(sbase, A0, lda, kc * BKC, tid);
            }
            CP_COMMIT();
            uint32_t sbase = sa0 + (c % NST) * GP<BKC>::STG;
            compute_stage<BKC>(sbase, sbase + GP<BKC>::ASTG, acc, wm, wn, lane);
        }
    }
    __syncthreads();

#pragma unroll
    for (int mt = 0; mt < 4; mt++) {
#pragma unroll
        for (int nt = 0; nt < 4; nt++) {
            int cl = wn * 32 + nt * 8 + tig * 2;
            int r = row0 + wm * 64 + mt * 16 + gid;
            float* a4 = acc[mt * 4 + nt];
            float sc0 = s_sc[cl], sc1 = s_sc[cl + 1];
            float sh0 = s_sh[cl], sh1 = s_sh[cl + 1];
            float bi0 = s_bi[cl], bi1 = s_bi[cl + 1];
            float x0 = fmaxf(a4[0] + bi0, 0.f) * sc0 + sh0;
            float x1 = fmaxf(a4[1] + bi1, 0.f) * sc1 + sh1;
            *reinterpret_cast<uint32_t*>(&Y[(long)r * 256 + col0 + cl]) = pkf16(x0, x1);
            x0 = fmaxf(a4[2] + bi0, 0.f) * sc0 + sh0;
            x1 = fmaxf(a4[3] + bi1, 0.f) * sc1 + sh1;
            *reinterpret_cast<uint32_t*>(&Y[(long)(r + 8) * 256 + col0 + cl]) = pkf16(x0, x1);
        }
    }
}

// ======================= dense GEMM + fused segment reduce (BKC=64) ==========
__global__ void __launch_bounds__(256, 2)
dense_gemm_h(const __half* __restrict__ X,
             const __half* __restrict__ Wh,
             const float* __restrict__ bz,
             const float* __restrict__ bnp,
             const int* __restrict__ mem,
             float* __restrict__ ssum,
             unsigned* __restrict__ smax)
{
    constexpr int BKC = 64;
    constexpr int NST = GP<BKC>::NST;
    extern __shared__ char dyn[];
    const uint32_t sa0 = smem_u32(dyn);
    __shared__ float s_sc[128], s_sh[128], s_bi[128];

    const int tid = threadIdx.x;
    const int lane = tid & 31, wid = tid >> 5;
    const int gid = lane >> 2, tig = lane & 3;
    const int wm = wid & 1, wn = wid >> 1;
    const int row0 = blockIdx.y * 128;
    const int col0 = blockIdx.x * 128;
    const int T = 4;

    if (tid < 128) {
        int c = col0 + tid;
        float gg = bnp[c], be = bnp[512 + c], mu = bnp[1024 + c], va = bnp[1536 + c];
        float sc = gg * rsqrtf(va + BN_EPS);
        s_sc[tid] = sc; s_sh[tid] = be - mu * sc; s_bi[tid] = bz[c];
    }

    const __half* A = X + (long)row0 * 256;
    float acc[16][4];
#pragma unroll
    for (int i = 0; i < 16; i++)
        acc[i][0] = acc[i][1] = acc[i][2] = acc[i][3] = 0.f;

#pragma unroll
    for (int c = 0; c < NST - 1; c++) {
        if (c < T) {
            uint32_t sbase = sa0 + (c % NST) * GP<BKC>::STG;
            issue_A<BKC>(sbase, A, 256, c * BKC, tid);
            issue_B<BKC>(sbase + GP<BKC>::ASTG, Wh, 512, col0, c * BKC, tid);
        }
        CP_COMMIT();
    }
    for (int c = 0; c < T; c++) {
        cp_wait<NST - 2>();
        __syncthreads();
        int n = c + NST - 1;
        if (n < T) {
            uint32_t sbase = sa0 + (n % NST) * GP<BKC>::STG;
            issue_A<BKC>(sbase, A, 256, n * BKC, tid);
            issue_B<BKC>(sbase + GP<BKC>::ASTG, Wh, 512, col0, n * BKC, tid);
        }
        CP_COMMIT();
        uint32_t sbase = sa0 + (c % NST) * GP<BKC>::STG;
        compute_stage<BKC>(sbase, sbase + GP<BKC>::ASTG, acc, wm, wn, lane);
    }
    __syncthreads();

#pragma unroll
    for (int mt = 0; mt < 4; mt++) {
        int r = row0 + wm * 64 + mt * 16 + gid;
        int m0 = mem[r] * 512, m1 = mem[r + 8] * 512;
#pragma unroll
        for (int nt = 0; nt < 4; nt++) {
            int cl = wn * 32 + nt * 8 + tig * 2;
            int gc = col0 + cl;
            float* a4 = acc[mt * 4 + nt];
            float sc0 = s_sc[cl], sc1 = s_sc[cl + 1];
            float sh0 = s_sh[cl], sh1 = s_sh[cl + 1];
            float bi0 = s_bi[cl], bi1 = s_bi[cl + 1];
            float x00 = fmaxf(a4[0] + bi0, 0.f) * sc0 + sh0;
            float x01 = fmaxf(a4[1] + bi1, 0.f) * sc1 + sh1;
            float x10 = fmaxf(a4[2] + bi0, 0.f) * sc0 + sh0;
            float x11 = fmaxf(a4[3] + bi1, 0.f) * sc1 + sh1;
            atomicAdd(&ssum[m0 + gc],     x00);
            atomicAdd(&ssum[m0 + gc + 1], x01);
            atomicAdd(&ssum[m1 + gc],     x10);
            atomicAdd(&ssum[m1 + gc + 1], x11);
            atomicMax(&smax[m0 + gc],     ford(x00));
            atomicMax(&smax[m0 + gc + 1], ford(x01));
            atomicMax(&smax[m1 + gc],     ford(x10));
            atomicMax(&smax[m1 + gc + 1], ford(x11));
        }
    }
}

// ======================= vectorized converts + seg init (8 outs/thread) ========
#define V_ATOM (65536L * 10)
#define V_W1   (9L * 80 * 32)
#define V_W2   (9L * 256 * 32)
#define V_WD   (256L * 64)
#define V_SEG  (1024L * 128)
__global__ void convert_all(const float* __restrict__ atomf,
                            const float* __restrict__ w1f,
                            const float* __restrict__ w2f,
                            const float* __restrict__ wdf,
                            __half* __restrict__ atomh, __half* __restrict__ w1h,
                            __half* __restrict__ w2h,   __half* __restrict__ wdh,
                            float* __restrict__ ssum,   unsigned* __restrict__ smax)
{
    long v = (long)blockIdx.x * blockDim.x + threadIdx.x;
    if (v < V_ATOM) {
        int row = (int)(v / 10), u = (int)(v - (long)row * 10);
        int k0 = u * 8;
        const float* src = atomf + (long)row * 75 + k0;
        uint32_t p[4];
#pragma unroll
        for (int q = 0; q < 4; q++) {
            float lo = (k0 + 2 * q     < 75) ? src[2 * q]     : 0.f;
            float hi = (k0 + 2 * q + 1 < 75) ? src[2 * q + 1] : 0.f;
            p[q] = pkf16(lo, hi);
        }
        *reinterpret_cast<uint4*>(atomh + (long)row * 80 + k0) =
            make_uint4(p[0], p[1], p[2], p[3]);
        return;
    }
    v -= V_ATOM;
    if (v < V_W1) {
        int n0 = (int)(v & 31) * 8;
        long t = v >> 5;
        int k = (int)(t % 80), g = (int)(t / 80);
        uint32_t p[4] = {0u, 0u, 0u, 0u};
        if (k < 75) {
            const float* s = w1f + ((long)g * 75 + k) * 256 + n0;
            float4 a = *reinterpret_cast<const float4*>(s);
            float4 b = *reinterpret_cast<const float4*>(s + 4);
            p[0] = pkf16(a.x, a.y); p[1] = pkf16(a.z, a.w);
            p[2] = pkf16(b.x, b.y); p[3] = pkf16(b.z, b.w);
        }
        *reinterpret_cast<uint4*>(w1h + ((long)g * 80 + k) * 256 + n0) =
            make_uint4(p[0], p[1], p[2], p[3]);
        return;
    }
    v -= V_W1;
    if (v < V_W2) {
        const float* s = w2f + v * 8;
        float4 a = *reinterpret_cast<const float4*>(s);
        float4 b = *reinterpret_cast<const float4*>(s + 4);
        *reinterpret_cast<uint4*>(w2h + v * 8) =
            make_uint4(pkf16(a.x, a.y), pkf16(a.z, a.w), pkf16(b.x, b.y), pkf16(b.z, b.w));
        return;
    }
    v -= V_W2;
    if (v < V_WD) {
        const float* s = wdf + v * 8;
        float4 a = *reinterpret_cast<const float4*>(s);
        float4 b = *reinterpret_cast<const float4*>(s + 4);
        *reinterpret_cast<uint4*>(wdh + v * 8) =
            make_uint4(pkf16(a.x, a.y), pkf16(a.z, a.w), pkf16(b.x, b.y), pkf16(b.z, b.w));
        return;
    }
    v -= V_WD;
    if (v < V_SEG) {
        *reinterpret_cast<float4*>(ssum + v * 4) = make_float4(0.f, 0.f, 0.f, 0.f);
        *reinterpret_cast<uint4*>(smax + v * 4) =
            make_uint4(0x007FFFFFu, 0x007FFFFFu, 0x007FFFFFu, 0x007FFFFFu);
    }
}

// ======================= pool =======================
__device__ __forceinline__ void max8(uint4& m, uint4 v) {
    *(__half2*)&m.x = __hmax2(*(__half2*)&m.x, *(__half2*)&v.x);
    *(__half2*)&m.y = __hmax2(*(__half2*)&m.y, *(__half2*)&v.y);
    *(__half2*)&m.z = __hmax2(*(__half2*)&m.z, *(__half2*)&v.z);
    *(__half2*)&m.w = __hmax2(*(__half2*)&m.w, *(__half2*)&v.w);
}

// 32 halves (2 x uint4) per thread; 16 threads per 256-col row (at DRAM floor)
__global__ void pool_all_h(const uint4* __restrict__ X,
                           const int* __restrict__ a1, const int* __restrict__ a2,
                           const int* __restrict__ a3, const int* __restrict__ a4,
                           uint4* __restrict__ out)
{
    long idx = (long)blockIdx.x * blockDim.x + threadIdx.x;
    if (idx >= 65536L * 16) return;
    int row = (int)(idx >> 4);
    int c = (int)(idx & 15) * 2;
    long base = (long)row * 32 + c;
    uint4 m0 = X[base], m1 = X[base + 1];
    if (row >= 4096) {
        const int* adj; int d, li;
        if (row < 16384)      { adj = a1; d = 1; li = row - 4096; }
        else if (row < 36864) { adj = a2; d = 2; li = row - 16384; }
        else if (row < 57344) { adj = a3; d = 3; li = row - 36864; }
        else                  { adj = a4; d = 4; li = row - 57344; }
        for (int j = 0; j < d; j++) {
            long nb = (long)adj[li * d + j] * 32 + c;
            max8(m0, X[nb]);
            max8(m1, X[nb + 1]);
        }
    }
    out[base] = m0;
    out[base + 1] = m1;
}

// ======================= head (+tanh fp write, warp-parallel GEMV) ===========
__global__ void head_kernel(const float* __restrict__ ssum,
                            const unsigned* __restrict__ smax,
                            const float* __restrict__ W,
                            const float* __restrict__ b,
                            float* __restrict__ soft,
                            float* __restrict__ logits,
                            float* __restrict__ out_fp)
{
    __shared__ float row[1024];
    __shared__ float lg[24];
    int bi = blockIdx.x;
    int tid = threadIdx.x, w = tid >> 5, lane = tid & 31;
    for (int c = tid; c < 1024; c += blockDim.x) {
        float v = (c < 512) ? ssum[bi * 512 + c] : funord(smax[bi * 512 + (c - 512)]);
        float t = tanhf(v);
        row[c] = t;
        out_fp[bi * 1024 + c] = t;
    }
    __syncthreads();
    for (int o = w; o < 24; o += 8) {
        float acc = 0.f;
        for (int k = lane; k < 1024; k += 32)
            acc += row[k] * W[k * 24 + o];
#pragma unroll
        for (int s = 16; s; s >>= 1)
            acc += __shfl_xor_sync(0xFFFFFFFFu, acc, s);
        if (lane == 0) lg[o] = acc + b[o];
    }
    __syncthreads();
    if (tid < 24) logits[bi * 24 + tid] = lg[tid];
    if (tid < 12) {
        float l0 = lg[2 * tid], l1 = lg[2 * tid + 1];
        float m  = fmaxf(l0, l1);
        float e0 = expf(l0 - m), e1 = expf(l1 - m);
        float inv = 1.f / (e0 + e1);
        soft[bi * 24 + 2 * tid]     = e0 * inv;
        soft[bi * 24 + 2 * tid + 1] = e1 * inv;
    }
}

// ======================= launch =======================
extern "C" void kernel_launch(void* const* d_in, const int* in_sizes, int n_in,
                              void* d_out, int out_size)
{
    const float* atom       = (const float*)d_in[0];
    const int*   membership = (const int*)  d_in[2];
    const int*   a1 = (const int*)d_in[4];
    const int*   a2 = (const int*)d_in[5];
    const int*   a3 = (const int*)d_in[6];
    const int*   a4 = (const int*)d_in[7];
    const float* gc1W = (const float*)d_in[8];
    const float* gc1b = (const float*)d_in[9];
    const float* gc2W = (const float*)d_in[10];
    const float* gc2b = (const float*)d_in[11];
    const float* bn1  = (const float*)d_in[12];
    const float* bn2  = (const float*)d_in[13];
    const float* bn3  = (const float*)d_in[14];
    const float* dW   = (const float*)d_in[15];
    const float* db   = (const float*)d_in[16];
    const float* hW   = (const float*)d_in[17];
    const float* hb   = (const float*)d_in[18];

    __half *atomh, *bufAh, *bufBh, *w1h, *w2h, *wdh;
    float *ssum; unsigned* smax;
    cudaGetSymbolAddress((void**)&atomh, g_atomh);
    cudaGetSymbolAddress((void**)&bufAh, g_bufAh);
    cudaGetSymbolAddress((void**)&bufBh, g_bufBh);
    cudaGetSymbolAddress((void**)&w1h,   g_w1h);
    cudaGetSymbolAddress((void**)&w2h,   g_w2h);
    cudaGetSymbolAddress((void**)&wdh,   g_wdh);
    cudaGetSymbolAddress((void**)&ssum,  g_sum);
    cudaGetSymbolAddress((void**)&smax,  g_maxu);

    cudaFuncSetAttribute(conv_gemm_t<80>, cudaFuncAttributeMaxDynamicSharedMemorySize,
                         GP<80>::SMEM);
    cudaFuncSetAttribute(conv_gemm_t<64>, cudaFuncAttributeMaxDynamicSharedMemorySize,
                         GP<64>::SMEM);
    cudaFuncSetAttribute(dense_gemm_h,    cudaFuncAttributeMaxDynamicSharedMemorySize,
                         GP<64>::SMEM);

    float* out        = (float*)d_out;
    float* out_soft   = out;
    float* out_logits = out + 1024 * 24;
    float* out_fp     = out + 2 * 1024 * 24;

    // vectorized converts + seg init (one launch)
    {
        long tot = V_ATOM + V_W1 + V_W2 + V_WD + V_SEG;
        convert_all<<<(int)((tot + 255) / 256), 256>>>(
            atom, gc1W, gc2W, dW, atomh, w1h, w2h, wdh, ssum, smax);
    }

    // layer 1 (K=80; fused neighbor-gather in rel pass)
    conv_gemm_t<80><<<dim3(2, 512), 256, GP<80>::SMEM>>>(
        atomh, 80, 1, w1h, gc1b, bn1, a1, a2, a3, a4, bufAh);
    pool_all_h<<<(int)((65536L * 16 + 255) / 256), 256>>>(
        (const uint4*)bufAh, a1, a2, a3, a4, (uint4*)bufBh);

    // layer 2 (K=256; BKC=64; fused neighbor-gather in rel pass)
    conv_gemm_t<64><<<dim3(2, 512), 256, GP<64>::SMEM>>>(
        bufBh, 256, 4, w2h, gc2b, bn2, a1, a2, a3, a4, bufAh);
    pool_all_h<<<(int)((65536L * 16 + 255) / 256), 256>>>(
        (const uint4*)bufAh, a1, a2, a3, a4, (uint4*)bufBh);

    // dense + BN3 + fused segment sum/max (BKC=64)
    dense_gemm_h<<<dim3(4, 512), 256, GP<64>::SMEM>>>(bufBh, wdh, db, bn3,
                                                      membership, ssum, smax);

    // head (+tanh fp write)
    head_kernel<<<1024, 256>>>(ssum, smax, hW, hb, out_soft, out_logits, out_fp);
}

// round 17
// speedup vs baseline: 1.0976x; 1.0976x over previous
#include <cuda_runtime.h>
#include <cuda_fp16.h>
#include <stdint.h>

#define BN_EPS 1e-3f

// Segment layout: atom rows d0 [0,4096) d1 [4096,16384) d2 [16384,36864) d3 [36864,57344) d4 [57344,65536)
// rel rows: d1 [0,12288) d2 [12288,32768) d3 [32768,53248) d4 [53248,61440)

// -------- scratch (static device globals) --------
__device__ __half   g_atomh[65536 * 80];
__device__ __half   g_relh [61440 * 256];
__device__ __half   g_bufAh[65536 * 256];
__device__ __half   g_bufBh[65536 * 256];
__device__ __half   g_w1h  [9 * 80 * 256];
__device__ __half   g_w2h  [9 * 256 * 256];
__device__ __half   g_wdh  [256 * 512];
__device__ float    g_sum  [1024 * 512];
__device__ unsigned g_maxu [1024 * 512];

// ======================= asm helpers =======================
__device__ __forceinline__ uint32_t smem_u32(const void* p) {
    uint32_t a;
    asm("{ .reg .u64 t; cvta.to.shared.u64 t, %1; cvt.u32.u64 %0, t; }" : "=r"(a) : "l"(p));
    return a;
}
__device__ __forceinline__ uint32_t pkf16(float lo, float hi) {
    uint32_t r; asm("cvt.rn.f16x2.f32 %0, %1, %2;" : "=r"(r) : "f"(hi), "f"(lo));
    return r;
}
__device__ __forceinline__ void cp16(uint32_t dst, const void* src) {
    asm volatile("cp.async.cg.shared.global [%0], [%1], 16;" :: "r"(dst), "l"(src));
}
#define CP_COMMIT() asm volatile("cp.async.commit_group;" ::: "memory")
template<int N>
__device__ __forceinline__ void cp_wait() {
    asm volatile("cp.async.wait_group %0;" :: "n"(N) : "memory");
}

__device__ __forceinline__ void ldsm_x4(uint32_t& r0, uint32_t& r1, uint32_t& r2, uint32_t& r3,
                                        uint32_t addr) {
    asm volatile("ldmatrix.sync.aligned.m8n8.x4.shared.b16 {%0,%1,%2,%3}, [%4];"
        : "=r"(r0), "=r"(r1), "=r"(r2), "=r"(r3) : "r"(addr));
}
__device__ __forceinline__ void ldsm_x2t(uint32_t& r0, uint32_t& r1, uint32_t addr) {
    asm volatile("ldmatrix.sync.aligned.m8n8.x2.trans.shared.b16 {%0,%1}, [%2];"
        : "=r"(r0), "=r"(r1) : "r"(addr));
}
__device__ __forceinline__ void mma16(float* d, const uint32_t* a, const uint32_t* b) {
    asm volatile("mma.sync.aligned.m16n8k16.row.col.f32.f16.f16.f32 "
        "{%0,%1,%2,%3}, {%4,%5,%6,%7}, {%8,%9}, {%0,%1,%2,%3};"
        : "+f"(d[0]), "+f"(d[1]), "+f"(d[2]), "+f"(d[3])
        : "r"(a[0]), "r"(a[1]), "r"(a[2]), "r"(a[3]), "r"(b[0]), "r"(b[1]));
}

__device__ __forceinline__ unsigned ford(float f) {
    unsigned u = __float_as_uint(f);
    return u ^ (unsigned)(((int)u >> 31) | 0x80000000);
}
__device__ __forceinline__ float funord(unsigned v) {
    unsigned u = (v & 0x80000000u) ? (v ^ 0x80000000u) : ~v;
    return __uint_as_float(u);
}

// ======================= GEMM pieces: 256 threads, 128x128 tile =======================
template<int BKC> struct GP {
    static constexpr int ARH  = BKC + 8;
    static constexpr int ASTG = 128 * ARH * 2;
    static constexpr int BSTG = BKC * 136 * 2;
    static constexpr int STG  = ASTG + BSTG;
    static constexpr int NST  = (BKC == 80) ? 2 : 3;
    static constexpr int SMEM = NST * STG;
};

template<int BKC>
__device__ __forceinline__ void issue_chunk(
    uint32_t sa, uint32_t sb,
    const __half* __restrict__ A, int lda,
    const __half* __restrict__ B, int ldb, int col0, int kt, int tid)
{
    constexpr int AU   = BKC / 8;
    constexpr int ATOT = 128 * AU;
    constexpr int APT  = ATOT / 256;
#pragma unroll
    for (int h = 0; h < APT; h++) {
        int id = tid + h * 256;
        int row = id / AU, u = id % AU;
        cp16(sa + (row * GP<BKC>::ARH + u * 8) * 2, A + (long)row * lda + kt + u * 8);
    }
    constexpr int BPT = BKC * 16 / 256;
#pragma unroll
    for (int h = 0; h < BPT; h++) {
        int id = tid + h * 256;
        int row = id >> 4, u = id & 15;
        cp16(sb + (row * 136 + u * 8) * 2, B + (long)(kt + row) * ldb + col0 + u * 8);
    }
}

template<int BKC>
__device__ __forceinline__ void compute_stage(
    uint32_t sa, uint32_t sb, float acc[16][4], int wm, int wn, int lane)
{
    const int arow = lane & 15, asel = (lane >> 4) * 8;
#pragma unroll
    for (int ks = 0; ks < BKC / 16; ks++) {
        uint32_t a[4][4];
#pragma unroll
        for (int mt = 0; mt < 4; mt++) {
            int m0 = wm * 64 + mt * 16;
            ldsm_x4(a[mt][0], a[mt][1], a[mt][2], a[mt][3],
                    sa + ((m0 + arow) * GP<BKC>::ARH + ks * 16 + asel) * 2);
        }
        uint32_t b[4][2];
        int krow = ks * 16 + (lane & 15);
#pragma unroll
        for (int nt = 0; nt < 4; nt++) {
            int n0 = wn * 32 + nt * 8;
            ldsm_x2t(b[nt][0], b[nt][1], sb + (krow * 136 + n0) * 2);
        }
#pragma unroll
        for (int mt = 0; mt < 4; mt++)
#pragma unroll
            for (int nt = 0; nt < 4; nt++)
                mma16(acc[mt * 4 + nt], a[mt], b[nt]);
    }
}

// ======================= conv GEMM (fp16, 128x128 CTA, 2 CTAs/SM) ==========
template<int BKC>
__global__ void __launch_bounds__(256, 2)
conv_gemm_t(const __half* __restrict__ X, int lda, int KCH,
            const __half* __restrict__ REL,
            const __half* __restrict__ Wh,
            const float* __restrict__ bz,
            const float* __restrict__ bnp,
            __half* __restrict__ Y)
{
    constexpr int NST = GP<BKC>::NST;
    extern __shared__ char dyn[];
    const uint32_t sa0 = smem_u32(dyn);
    __shared__ float s_sc[128], s_sh[128], s_bi[128];

    const int tid = threadIdx.x;
    const int lane = tid & 31, wid = tid >> 5;
    const int gid = lane >> 2, tig = lane & 3;
    const int wm = wid & 1, wn = wid >> 1;
    const int row0 = blockIdx.y * 128;
    const int col0 = blockIdx.x * 128;
    const int d = (row0 < 4096) ? 0 : (row0 < 16384) ? 1 : (row0 < 36864) ? 2
                : (row0 < 57344) ? 3 : 4;

    if (tid < 128) {
        int c = col0 + tid;
        float bias = (d == 0) ? bz[8 * 256 + c]
                              : bz[(2 * d - 2) * 256 + c] + bz[(2 * d - 1) * 256 + c];
        float gg = bnp[c], be = bnp[256 + c], mu = bnp[512 + c], va = bnp[768 + c];
        float sc = gg * rsqrtf(va + BN_EPS);
        s_sc[tid] = sc; s_sh[tid] = be - mu * sc; s_bi[tid] = bias;
    }

    const long wsz = (long)lda * 256;
    const __half* A0 = X + (long)row0 * lda;
    const __half* W0 = Wh + ((d == 0) ? 8 : (2 * d - 1)) * wsz;
    const __half* A1 = (d > 0) ? REL + (long)(row0 - 4096) * lda : A0;
    const __half* W1 = (d > 0) ? Wh + (2 * d - 2) * wsz : W0;
    const int T = ((d > 0) ? 2 : 1) * KCH;

    float acc[16][4];
#pragma unroll
    for (int i = 0; i < 16; i++)
        acc[i][0] = acc[i][1] = acc[i][2] = acc[i][3] = 0.f;

    if constexpr (BKC == 80) {
        // conv1 specialized path: T in {1,2}, NST=2; issue ALL chunks upfront
        issue_chunk<BKC>(sa0, sa0 + GP<BKC>::ASTG, A0, lda, W0, 256, col0, 0, tid);
        CP_COMMIT();
        if (T == 2) {
            uint32_t sb1 = sa0 + GP<BKC>::STG;
            issue_chunk<BKC>(sb1, sb1 + GP<BKC>::ASTG, A1, lda, W1, 256, col0, 0, tid);
            CP_COMMIT();
            cp_wait<1>();
            __syncthreads();
            compute_stage<BKC>(sa0, sa0 + GP<BKC>::ASTG, acc, wm, wn, lane);
            cp_wait<0>();
            __syncthreads();
            compute_stage<BKC>(sb1, sb1 + GP<BKC>::ASTG, acc, wm, wn, lane);
        } else {
            cp_wait<0>();
            __syncthreads();
            compute_stage<BKC>(sa0, sa0 + GP<BKC>::ASTG, acc, wm, wn, lane);
        }
    } else {
#pragma unroll
        for (int c = 0; c < NST - 1; c++) {
            if (c < T) {
                int pass = (c >= KCH), kc = c - pass * KCH;
                uint32_t sbase = sa0 + (c % NST) * GP<BKC>::STG;
                issue_chunk<BKC>(sbase, sbase + GP<BKC>::ASTG,
                                 pass ? A1 : A0, lda, pass ? W1 : W0, 256, col0,
                                 kc * BKC, tid);
            }
            CP_COMMIT();
        }
        for (int c = 0; c < T; c++) {
            cp_wait<NST - 2>();
            __syncthreads();
            int n = c + NST - 1;
            if (n < T) {
                int pass = (n >= KCH), kc = n - pass * KCH;
                uint32_t sbase = sa0 + (n % NST) * GP<BKC>::STG;
                issue_chunk<BKC>(sbase, sbase + GP<BKC>::ASTG,
                                 pass ? A1 : A0, lda, pass ? W1 : W0, 256, col0,
                                 kc * BKC, tid);
            }
            CP_COMMIT();
            uint32_t sbase = sa0 + (c % NST) * GP<BKC>::STG;
            compute_stage<BKC>(sbase, sbase + GP<BKC>::ASTG, acc, wm, wn, lane);
        }
    }
    __syncthreads();

#pragma unroll
    for (int mt = 0; mt < 4; mt++) {
#pragma unroll
        for (int nt = 0; nt < 4; nt++) {
            int cl = wn * 32 + nt * 8 + tig * 2;
            int r = row0 + wm * 64 + mt * 16 + gid;
            float* a4 = acc[mt * 4 + nt];
            float sc0 = s_sc[cl], sc1 = s_sc[cl + 1];
            float sh0 = s_sh[cl], sh1 = s_sh[cl + 1];
            float bi0 = s_bi[cl], bi1 = s_bi[cl + 1];
            float x0 = fmaxf(a4[0] + bi0, 0.f) * sc0 + sh0;
            float x1 = fmaxf(a4[1] + bi1, 0.f) * sc1 + sh1;
            *reinterpret_cast<uint32_t*>(&Y[(long)r * 256 + col0 + cl]) = pkf16(x0, x1);
            x0 = fmaxf(a4[2] + bi0, 0.f) * sc0 + sh0;
            x1 = fmaxf(a4[3] + bi1, 0.f) * sc1 + sh1;
            *reinterpret_cast<uint32_t*>(&Y[(long)(r + 8) * 256 + col0 + cl]) = pkf16(x0, x1);
        }
    }
}

// ======================= dense GEMM + fused segment reduce (BKC=64) ==========
__global__ void __launch_bounds__(256, 2)
dense_gemm_h(const __half* __restrict__ X,
             const __half* __restrict__ Wh,
             const float* __restrict__ bz,
             const float* __restrict__ bnp,
             const int* __restrict__ mem,
             float* __restrict__ ssum,
             unsigned* __restrict__ smax)
{
    constexpr int BKC = 64;
    constexpr int NST = GP<BKC>::NST;
    extern __shared__ char dyn[];
    const uint32_t sa0 = smem_u32(dyn);
    __shared__ float s_sc[128], s_sh[128], s_bi[128];

    const int tid = threadIdx.x;
    const int lane = tid & 31, wid = tid >> 5;
    const int gid = lane >> 2, tig = lane & 3;
    const int wm = wid & 1, wn = wid >> 1;
    const int row0 = blockIdx.y * 128;
    const int col0 = blockIdx.x * 128;
    const int T = 4;

    if (tid < 128) {
        int c = col0 + tid;
        float gg = bnp[c], be = bnp[512 + c], mu = bnp[1024 + c], va = bnp[1536 + c];
        float sc = gg * rsqrtf(va + BN_EPS);
        s_sc[tid] = sc; s_sh[tid] = be - mu * sc; s_bi[tid] = bz[c];
    }

    const __half* A = X + (long)row0 * 256;
    float acc[16][4];
#pragma unroll
    for (int i = 0; i < 16; i++)
        acc[i][0] = acc[i][1] = acc[i][2] = acc[i][3] = 0.f;

#pragma unroll
    for (int c = 0; c < NST - 1; c++) {
        if (c < T) {
            uint32_t sbase = sa0 + (c % NST) * GP<BKC>::STG;
            issue_chunk<BKC>(sbase, sbase + GP<BKC>::ASTG, A, 256, Wh, 512, col0,
                             c * BKC, tid);
        }
        CP_COMMIT();
    }
    for (int c = 0; c < T; c++) {
        cp_wait<NST - 2>();
        __syncthreads();
        int n = c + NST - 1;
        if (n < T) {
            uint32_t sbase = sa0 + (n % NST) * GP<BKC>::STG;
            issue_chunk<BKC>(sbase, sbase + GP<BKC>::ASTG, A, 256, Wh, 512, col0,
                             n * BKC, tid);
        }
        CP_COMMIT();
        uint32_t sbase = sa0 + (c % NST) * GP<BKC>::STG;
        compute_stage<BKC>(sbase, sbase + GP<BKC>::ASTG, acc, wm, wn, lane);
    }
    __syncthreads();

#pragma unroll
    for (int mt = 0; mt < 4; mt++) {
        int r = row0 + wm * 64 + mt * 16 + gid;
        int m0 = mem[r] * 512, m1 = mem[r + 8] * 512;
#pragma unroll
        for (int nt = 0; nt < 4; nt++) {
            int cl = wn * 32 + nt * 8 + tig * 2;
            int gc = col0 + cl;
            float* a4 = acc[mt * 4 + nt];
            float sc0 = s_sc[cl], sc1 = s_sc[cl + 1];
            float sh0 = s_sh[cl], sh1 = s_sh[cl + 1];
            float bi0 = s_bi[cl], bi1 = s_bi[cl + 1];
            float x00 = fmaxf(a4[0] + bi0, 0.f) * sc0 + sh0;
            float x01 = fmaxf(a4[1] + bi1, 0.f) * sc1 + sh1;
            float x10 = fmaxf(a4[2] + bi0, 0.f) * sc0 + sh0;
            float x11 = fmaxf(a4[3] + bi1, 0.f) * sc1 + sh1;
            atomicAdd(&ssum[m0 + gc],     x00);
            atomicAdd(&ssum[m0 + gc + 1], x01);
            atomicAdd(&ssum[m1 + gc],     x10);
            atomicAdd(&ssum[m1 + gc + 1], x11);
            atomicMax(&smax[m0 + gc],     ford(x00));
            atomicMax(&smax[m0 + gc + 1], ford(x01));
            atomicMax(&smax[m1 + gc],     ford(x10));
            atomicMax(&smax[m1 + gc + 1], ford(x11));
        }
    }
}

// ======================= vectorized converts + seg init (8 outs/thread) ========
#define V_ATOM (65536L * 10)
#define V_W1   (9L * 80 * 32)
#define V_W2   (9L * 256 * 32)
#define V_WD   (256L * 64)
#define V_SEG  (1024L * 128)
__global__ void convert_all(const float* __restrict__ atomf,
                            const float* __restrict__ w1f,
                            const float* __restrict__ w2f,
                            const float* __restrict__ wdf,
                            __half* __restrict__ atomh, __half* __restrict__ w1h,
                            __half* __restrict__ w2h,   __half* __restrict__ wdh,
                            float* __restrict__ ssum,   unsigned* __restrict__ smax)
{
    long v = (long)blockIdx.x * blockDim.x + threadIdx.x;
    if (v < V_ATOM) {
        int row = (int)(v / 10), u = (int)(v - (long)row * 10);
        int k0 = u * 8;
        const float* src = atomf + (long)row * 75 + k0;
        uint32_t p[4];
#pragma unroll
        for (int q = 0; q < 4; q++) {
            float lo = (k0 + 2 * q     < 75) ? src[2 * q]     : 0.f;
            float hi = (k0 + 2 * q + 1 < 75) ? src[2 * q + 1] : 0.f;
            p[q] = pkf16(lo, hi);
        }
        *reinterpret_cast<uint4*>(atomh + (long)row * 80 + k0) =
            make_uint4(p[0], p[1], p[2], p[3]);
        return;
    }
    v -= V_ATOM;
    if (v < V_W1) {
        int n0 = (int)(v & 31) * 8;
        long t = v >> 5;
        int k = (int)(t % 80), g = (int)(t / 80);
        uint32_t p[4] = {0u, 0u, 0u, 0u};
        if (k < 75) {
            const float* s = w1f + ((long)g * 75 + k) * 256 + n0;
            float4 a = *reinterpret_cast<const float4*>(s);
            float4 b = *reinterpret_cast<const float4*>(s + 4);
            p[0] = pkf16(a.x, a.y); p[1] = pkf16(a.z, a.w);
            p[2] = pkf16(b.x, b.y); p[3] = pkf16(b.z, b.w);
        }
        *reinterpret_cast<uint4*>(w1h + ((long)g * 80 + k) * 256 + n0) =
            make_uint4(p[0], p[1], p[2], p[3]);
        return;
    }
    v -= V_W1;
    if (v < V_W2) {
        const float* s = w2f + v * 8;
        float4 a = *reinterpret_cast<const float4*>(s);
        float4 b = *reinterpret_cast<const float4*>(s + 4);
        *reinterpret_cast<uint4*>(w2h + v * 8) =
            make_uint4(pkf16(a.x, a.y), pkf16(a.z, a.w), pkf16(b.x, b.y), pkf16(b.z, b.w));
        return;
    }
    v -= V_W2;
    if (v < V_WD) {
        const float* s = wdf + v * 8;
        float4 a = *reinterpret_cast<const float4*>(s);
        float4 b = *reinterpret_cast<const float4*>(s + 4);
        *reinterpret_cast<uint4*>(wdh + v * 8) =
            make_uint4(pkf16(a.x, a.y), pkf16(a.z, a.w), pkf16(b.x, b.y), pkf16(b.z, b.w));
        return;
    }
    v -= V_WD;
    if (v < V_SEG) {
        *reinterpret_cast<float4*>(ssum + v * 4) = make_float4(0.f, 0.f, 0.f, 0.f);
        *reinterpret_cast<uint4*>(smax + v * 4) =
            make_uint4(0x007FFFFFu, 0x007FFFFFu, 0x007FFFFFu, 0x007FFFFFu);
    }
}

// ======================= gather / pool =======================
__device__ __forceinline__ void acc8(float2 s[4], uint4 v) {
    s[0].x += __low2float(*(__half2*)&v.x);  s[0].y += __high2float(*(__half2*)&v.x);
    s[1].x += __low2float(*(__half2*)&v.y);  s[1].y += __high2float(*(__half2*)&v.y);
    s[2].x += __low2float(*(__half2*)&v.z);  s[2].y += __high2float(*(__half2*)&v.z);
    s[3].x += __low2float(*(__half2*)&v.w);  s[3].y += __high2float(*(__half2*)&v.w);
}

template<int CH>
__global__ void gather_all_h(const __half* __restrict__ X,
                             const int* __restrict__ a1, const int* __restrict__ a2,
                             const int* __restrict__ a3, const int* __restrict__ a4,
                             __half* __restrict__ out)
{
    constexpr int LD = CH * 8;
    long idx = (long)blockIdx.x * blockDim.x + threadIdx.x;
    if (idx >= 61440L * CH) return;
    int i = (int)(idx / CH);
    int c = (int)(idx - (long)i * CH) * 8;
    const int* adj; int d, li;
    if (i < 12288)      { adj = a1; d = 1; li = i; }
    else if (i < 32768) { adj = a2; d = 2; li = i - 12288; }
    else if (i < 53248) { adj = a3; d = 3; li = i - 32768; }
    else                { adj = a4; d = 4; li = i - 53248; }
    float2 s[4];
    s[0] = s[1] = s[2] = s[3] = make_float2(0.f, 0.f);
    for (int j = 0; j < d; j++) {
        uint4 v = *reinterpret_cast<const uint4*>(X + (long)adj[li * d + j] * LD + c);
        acc8(s, v);
    }
    uint4 o;
    o.x = pkf16(s[0].x, s[0].y); o.y = pkf16(s[1].x, s[1].y);
    o.z = pkf16(s[2].x, s[2].y); o.w = pkf16(s[3].x, s[3].y);
    *reinterpret_cast<uint4*>(out + (long)i * LD + c) = o;
}

__device__ __forceinline__ void max8(uint4& m, uint4 v) {
    *(__half2*)&m.x = __hmax2(*(__half2*)&m.x, *(__half2*)&v.x);
    *(__half2*)&m.y = __hmax2(*(__half2*)&m.y, *(__half2*)&v.y);
    *(__half2*)&m.z = __hmax2(*(__half2*)&m.z, *(__half2*)&v.z);
    *(__half2*)&m.w = __hmax2(*(__half2*)&m.w, *(__half2*)&v.w);
}

// 32 halves (2 x uint4) per thread; 16 threads per 256-col row (at DRAM floor)
__global__ void pool_all_h(const uint4* __restrict__ X,
                           const int* __restrict__ a1, const int* __restrict__ a2,
                           const int* __restrict__ a3, const int* __restrict__ a4,
                           uint4* __restrict__ out)
{
    long idx = (long)blockIdx.x * blockDim.x + threadIdx.x;
    if (idx >= 65536L * 16) return;
    int row = (int)(idx >> 4);
    int c = (int)(idx & 15) * 2;
    long base = (long)row * 32 + c;
    uint4 m0 = X[base], m1 = X[base + 1];
    if (row >= 4096) {
        const int* adj; int d, li;
        if (row < 16384)      { adj = a1; d = 1; li = row - 4096; }
        else if (row < 36864) { adj = a2; d = 2; li = row - 16384; }
        else if (row < 57344) { adj = a3; d = 3; li = row - 36864; }
        else                  { adj = a4; d = 4; li = row - 57344; }
        for (int j = 0; j < d; j++) {
            long nb = (long)adj[li * d + j] * 32 + c;
            max8(m0, X[nb]);
            max8(m1, X[nb + 1]);
        }
    }
    out[base] = m0;
    out[base + 1] = m1;
}

// ======================= head (+tanh fp write, warp-parallel GEMV) ===========
__global__ void head_kernel(const float* __restrict__ ssum,
                            const unsigned* __restrict__ smax,
                            const float* __restrict__ W,
                            const float* __restrict__ b,
                            float* __restrict__ soft,
                            float* __restrict__ logits,
                            float* __restrict__ out_fp)
{
    __shared__ float row[1024];
    __shared__ float lg[24];
    int bi = blockIdx.x;
    int tid = threadIdx.x, w = tid >> 5, lane = tid & 31;
    for (int c = tid; c < 1024; c += blockDim.x) {
        float v = (c < 512) ? ssum[bi * 512 + c] : funord(smax[bi * 512 + (c - 512)]);
        float t = tanhf(v);
        row[c] = t;
        out_fp[bi * 1024 + c] = t;
    }
    __syncthreads();
    for (int o = w; o < 24; o += 8) {
        float acc = 0.f;
        for (int k = lane; k < 1024; k += 32)
            acc += row[k] * W[k * 24 + o];
#pragma unroll
        for (int s = 16; s; s >>= 1)
            acc += __shfl_xor_sync(0xFFFFFFFFu, acc, s);
        if (lane == 0) lg[o] = acc + b[o];
    }
    __syncthreads();
    if (tid < 24) logits[bi * 24 + tid] = lg[tid];
    if (tid < 12) {
        float l0 = lg[2 * tid], l1 = lg[2 * tid + 1];
        float m  = fmaxf(l0, l1);
        float e0 = expf(l0 - m), e1 = expf(l1 - m);
        float inv = 1.f / (e0 + e1);
        soft[bi * 24 + 2 * tid]     = e0 * inv;
        soft[bi * 24 + 2 * tid + 1] = e1 * inv;
    }
}

// ======================= launch =======================
extern "C" void kernel_launch(void* const* d_in, const int* in_sizes, int n_in,
                              void* d_out, int out_size)
{
    const float* atom       = (const float*)d_in[0];
    const int*   membership = (const int*)  d_in[2];
    const int*   a1 = (const int*)d_in[4];
    const int*   a2 = (const int*)d_in[5];
    const int*   a3 = (const int*)d_in[6];
    const int*   a4 = (const int*)d_in[7];
    const float* gc1W = (const float*)d_in[8];
    const float* gc1b = (const float*)d_in[9];
    const float* gc2W = (const float*)d_in[10];
    const float* gc2b = (const float*)d_in[11];
    const float* bn1  = (const float*)d_in[12];
    const float* bn2  = (const float*)d_in[13];
    const float* bn3  = (const float*)d_in[14];
    const float* dW   = (const float*)d_in[15];
    const float* db   = (const float*)d_in[16];
    const float* hW   = (const float*)d_in[17];
    const float* hb   = (const float*)d_in[18];

    __half *atomh, *relh, *bufAh, *bufBh, *w1h, *w2h, *wdh;
    float *ssum; unsigned* smax;
    cudaGetSymbolAddress((void**)&atomh, g_atomh);
    cudaGetSymbolAddress((void**)&relh,  g_relh);
    cudaGetSymbolAddress((void**)&bufAh, g_bufAh);
    cudaGetSymbolAddress((void**)&bufBh, g_bufBh);
    cudaGetSymbolAddress((void**)&w1h,   g_w1h);
    cudaGetSymbolAddress((void**)&w2h,   g_w2h);
    cudaGetSymbolAddress((void**)&wdh,   g_wdh);
    cudaGetSymbolAddress((void**)&ssum,  g_sum);
    cudaGetSymbolAddress((void**)&smax,  g_maxu);

    cudaFuncSetAttribute(conv_gemm_t<80>, cudaFuncAttributeMaxDynamicSharedMemorySize,
                         GP<80>::SMEM);
    cudaFuncSetAttribute(conv_gemm_t<64>, cudaFuncAttributeMaxDynamicSharedMemorySize,
                         GP<64>::SMEM);
    cudaFuncSetAttribute(dense_gemm_h,    cudaFuncAttributeMaxDynamicSharedMemorySize,
                         GP<64>::SMEM);

    float* out        = (float*)d_out;
    float* out_soft   = out;
    float* out_logits = out + 1024 * 24;
    float* out_fp     = out + 2 * 1024 * 24;

    // vectorized converts + seg init (one launch)
    {
        long tot = V_ATOM + V_W1 + V_W2 + V_WD + V_SEG;
        convert_all<<<(int)((tot + 255) / 256), 256>>>(
            atom, gc1W, gc2W, dW, atomh, w1h, w2h, wdh, ssum, smax);
    }

    // layer 1 (padded K=80; BKC=80, both chunks issued upfront)
    gather_all_h<10><<<(int)((61440L * 10 + 255) / 256), 256>>>(
        atomh, a1, a2, a3, a4, relh);
    conv_gemm_t<80><<<dim3(2, 512), 256, GP<80>::SMEM>>>(
        atomh, 80, 1, relh, w1h, gc1b, bn1, bufAh);
    pool_all_h<<<(int)((65536L * 16 + 255) / 256), 256>>>(
        (const uint4*)bufAh, a1, a2, a3, a4, (uint4*)bufBh);

    // layer 2 (K=256; BKC=64, 4 chunks/pass)
    gather_all_h<32><<<(int)((61440L * 32 + 255) / 256), 256>>>(
        bufBh, a1, a2, a3, a4, relh);
    conv_gemm_t<64><<<dim3(2, 512), 256, GP<64>::SMEM>>>(
        bufBh, 256, 4, relh, w2h, gc2b, bn2, bufAh);
    pool_all_h<<<(int)((65536L * 16 + 255) / 256), 256>>>(
        (const uint4*)bufAh, a1, a2, a3, a4, (uint4*)bufBh);

    // dense + BN3 + fused segment sum/max (BKC=64)
    dense_gemm_h<<<dim3(4, 512), 256, GP<64>::SMEM>>>(bufBh, wdh, db, bn3,
                                                      membership, ssum, smax);

    // head (+tanh fp write)
    head_kernel<<<1024, 256>>>(ssum, smax, hW, hb, out_soft, out_logits, out_fp);
}